// round 1
// baseline (speedup 1.0000x reference)
#include <cuda_runtime.h>
#include <math.h>

// Problem constants: N=4, P1=P2=2048, D=64
#define NB 4
#define PP 2048
#define DD 64
#define EPSR     0.1f
#define INV_EPS  10.0f
#define THRESHV  0.1f
#define MAXIT    50
#define NPITEMS  (NB * PP * PP)          // 16777216 elements per [N,P1,P2] tensor
// log(1/2048 + 1e-8) in fp32
#define LOGMU    (-7.6245985f)

#define NEG_INF  (-__int_as_float(0x7f800000) * 1.0f)

// ---------------- device scratch (static: no allocations allowed) ----------
__device__ float g_S[DD * DD];           // M + M^T
__device__ float g_XS[NB * PP * DD];     // x @ S  [N,P1,D]
__device__ float g_dx[NB * PP];          // x_i M x_i^T
__device__ float g_dy[NB * PP];          // y_j M y_j^T
__device__ float g_u[NB * PP];
__device__ float g_v[NB * PP];
__device__ float g_duabs[NB * PP];       // per-row |u_new - u_old|
__device__ float g_cpart[4096];          // cost partials
__device__ int   g_counter[64];          // per-iteration last-block counters
__device__ int   g_active;

// ---------------- init: S = M + M^T, zero u/v, reset flags -----------------
__global__ void initk(const float* __restrict__ M) {
    int t = threadIdx.x;  // 1024 threads, 1 block
    for (int idx = t; idx < DD * DD; idx += 1024) {
        int d = idx >> 6, e = idx & 63;
        g_S[idx] = M[idx] + M[(e << 6) + d];
    }
    for (int idx = t; idx < NB * PP; idx += 1024) {
        g_u[idx] = 0.0f;
        g_v[idx] = 0.0f;
    }
    if (t < 64) g_counter[t] = 0;
    if (t == 0) g_active = 1;
}

// ---------------- prep: XS = x@S, dx = 0.5*rowdot(XS,x), dy likewise -------
// grid = 2*NB*PP blocks of 64 threads; block r handles one row.
__global__ void prepk(const float* __restrict__ x, const float* __restrict__ y) {
    __shared__ float row[DD];
    __shared__ float red[DD];
    int r = blockIdx.x;
    int e = threadIdx.x;
    bool is_x = (r < NB * PP);
    const float* src = is_x ? (x + ((size_t)r << 6))
                            : (y + ((size_t)(r - NB * PP) << 6));
    row[e] = src[e];
    __syncthreads();
    float acc = 0.0f;
#pragma unroll
    for (int d = 0; d < DD; d++) acc = fmaf(row[d], g_S[(d << 6) + e], acc);
    if (is_x) g_XS[((size_t)r << 6) + e] = acc;
    red[e] = acc * row[e];
    __syncthreads();
    for (int o = 32; o > 0; o >>= 1) {
        if (e < o) red[e] += red[e + o];
        __syncthreads();
    }
    if (e == 0) {
        float dval = 0.5f * red[0];   // x S x^T / 2 = x M x^T
        if (is_x) g_dx[r] = dval;
        else      g_dy[r - NB * PP] = dval;
    }
}

// ---------------- C build: C[n,i,j] = dx_i + dy_j - XS_i . y_j -------------
// 64x64 tiles, 256 threads, 4x4 micro-tile per thread, K=64 fully staged.
__global__ void cbuildk(const float* __restrict__ y, float* __restrict__ C) {
    __shared__ float As[64][65];   // As[k][i] = XS[n][i0+i][k]
    __shared__ float Bs[64][65];   // Bs[k][j] = y [n][j0+j][k]
    int n = blockIdx.z;
    int i0 = blockIdx.y << 6;
    int j0 = blockIdx.x << 6;
    int tid = threadIdx.x;

    const float* XSb = g_XS + ((size_t)(n * PP + i0) << 6);
    const float* Yb  = y    + ((size_t)(n * PP + j0) << 6);
#pragma unroll
    for (int t = 0; t < 16; t++) {
        int idx = tid + (t << 8);
        int row = idx >> 6, k = idx & 63;
        As[k][row] = XSb[idx];
        Bs[k][row] = Yb[idx];
    }
    __syncthreads();

    int tx = tid & 15, ty = tid >> 4;
    float acc[4][4];
#pragma unroll
    for (int a = 0; a < 4; a++)
#pragma unroll
        for (int b = 0; b < 4; b++) acc[a][b] = 0.0f;

#pragma unroll 8
    for (int k = 0; k < 64; k++) {
        float av[4], bv[4];
#pragma unroll
        for (int q = 0; q < 4; q++) {
            av[q] = As[k][(ty << 2) + q];
            bv[q] = Bs[k][(tx << 2) + q];
        }
#pragma unroll
        for (int a = 0; a < 4; a++)
#pragma unroll
            for (int b = 0; b < 4; b++)
                acc[a][b] = fmaf(av[a], bv[b], acc[a][b]);
    }

    float dxr[4], dyr[4];
#pragma unroll
    for (int q = 0; q < 4; q++) {
        dxr[q] = g_dx[n * PP + i0 + (ty << 2) + q];
        dyr[q] = g_dy[n * PP + j0 + (tx << 2) + q];
    }
#pragma unroll
    for (int a = 0; a < 4; a++) {
        float4 out;
        out.x = dxr[a] + dyr[0] - acc[a][0];
        out.y = dxr[a] + dyr[1] - acc[a][1];
        out.z = dxr[a] + dyr[2] - acc[a][2];
        out.w = dxr[a] + dyr[3] - acc[a][3];
        size_t off = ((size_t)(n * PP + i0 + (ty << 2) + a) << 11) + j0 + (tx << 2);
        *reinterpret_cast<float4*>(C + off) = out;
    }
}

// ---------------- U pass: row-wise LSE of (v_j - C_ij)/eps -----------------
// grid = NB*PP/8 blocks of 256 (8 warps = 8 rows per block).
__global__ void ukern(const float* __restrict__ C) {
    if (!g_active) return;
    __shared__ float vs[PP];
    int warp = threadIdx.x >> 5, lane = threadIdx.x & 31;
    int r = blockIdx.x * 8 + warp;       // global row in [0, NB*PP)
    int n = r >> 11;
    for (int t = threadIdx.x; t < PP; t += 256) vs[t] = g_v[(n << 11) + t];
    __syncthreads();

    const float* Crow = C + ((size_t)r << 11);
    float m = NEG_INF;
#pragma unroll 8
    for (int k = 0; k < 64; k++) {
        int j = lane + (k << 5);
        float z = (vs[j] - Crow[j]) * INV_EPS;
        m = fmaxf(m, z);
    }
#pragma unroll
    for (int o = 16; o > 0; o >>= 1) m = fmaxf(m, __shfl_xor_sync(0xffffffffu, m, o));

    float s = 0.0f;
#pragma unroll 8
    for (int k = 0; k < 64; k++) {
        int j = lane + (k << 5);
        float z = (vs[j] - Crow[j]) * INV_EPS;
        s += __expf(z - m);
    }
#pragma unroll
    for (int o = 16; o > 0; o >>= 1) s += __shfl_xor_sync(0xffffffffu, s, o);

    if (lane == 0) {
        float lse  = m + logf(s);
        float unew = EPSR * LOGMU - EPSR * lse;
        float uold = g_u[r];
        g_duabs[r] = fabsf(unew - uold);
        g_u[r] = unew;
    }
}

// ---------------- V pass: col-wise LSE of (u_i - C_ij)/eps -----------------
// grid = NB*(PP/32) = 256 blocks of 512 threads.
// Block: 32 columns x 16 row-segments (128 rows each). Last finished block
// computes err and updates g_active (deterministic fixed-tree reduction).
__global__ void vkern(const float* __restrict__ C, int it) {
    if (!g_active) return;
    __shared__ float us[PP];
    __shared__ float pm[16][33];
    __shared__ float ps[16][33];
    __shared__ float red[512];
    __shared__ int   lastFlag;

    int tid = threadIdx.x;
    int n  = blockIdx.x >> 6;
    int j0 = (blockIdx.x & 63) << 5;
    for (int t = tid; t < PP; t += 512) us[t] = g_u[(n << 11) + t];
    __syncthreads();

    int c = tid & 31, seg = tid >> 5;
    const float* Cb = C + ((size_t)n << 22) + j0 + c;
    int ibase = seg << 7;

    float m = NEG_INF, s = 0.0f;
    for (int t8 = 0; t8 < 16; t8++) {
        int i0 = ibase + (t8 << 3);
        float z[8];
        float mc = NEG_INF;
#pragma unroll
        for (int q = 0; q < 8; q++) {
            int i = i0 + q;
            z[q] = (us[i] - Cb[(size_t)i << 11]) * INV_EPS;
            mc = fmaxf(mc, z[q]);
        }
        float sc = 0.0f;
#pragma unroll
        for (int q = 0; q < 8; q++) sc += __expf(z[q] - mc);
        float m2 = fmaxf(m, mc);
        s = s * __expf(m - m2) + sc * __expf(mc - m2);
        m = m2;
    }
    pm[seg][c] = m;
    ps[seg][c] = s;
    __syncthreads();

    if (tid < 32) {
        float M = NEG_INF;
#pragma unroll
        for (int sg = 0; sg < 16; sg++) M = fmaxf(M, pm[sg][tid]);
        float S = 0.0f;
#pragma unroll
        for (int sg = 0; sg < 16; sg++) S += ps[sg][tid] * __expf(pm[sg][tid] - M);
        float lse = M + logf(S);
        g_v[(n << 11) + j0 + tid] = EPSR * LOGMU - EPSR * lse;
    }

    // last-block: err = mean_n sum_i |du| ; active &= (err >= THRESH)
    if (tid == 0) {
        __threadfence();
        int old = atomicAdd(&g_counter[it], 1);
        lastFlag = (old == (int)gridDim.x - 1);
    }
    __syncthreads();
    if (lastFlag) {
        float acc = 0.0f;
        for (int t = tid; t < NB * PP; t += 512) acc += g_duabs[t];
        red[tid] = acc;
        __syncthreads();
        for (int o = 256; o > 0; o >>= 1) {
            if (tid < o) red[tid] += red[tid + o];
            __syncthreads();
        }
        if (tid == 0) {
            float err = red[0] * (1.0f / (float)NB);
            if (err < THRESHV) g_active = 0;
        }
    }
}

// ---------------- final: pi = exp((-C+u+v)/eps), cost partials -------------
// grid 4096 blocks x 256 threads, 16 elems/thread; deterministic block reduce.
__global__ void fink(const float* __restrict__ C, float* __restrict__ pi) {
    __shared__ float red[256];
    int tid = threadIdx.x;
    size_t base = (size_t)blockIdx.x * 4096;
    float acc = 0.0f;
#pragma unroll
    for (int t = 0; t < 16; t++) {
        size_t idx = base + tid + (t << 8);
        int n   = (int)(idx >> 22);
        int rem = (int)(idx & 4194303);
        int i   = rem >> 11;
        int j   = rem & 2047;
        float Cv = C[idx];
        float z  = (g_u[(n << 11) + i] + g_v[(n << 11) + j] - Cv) * INV_EPS;
        float p  = __expf(z);
        pi[idx]  = p;
        acc = fmaf(p, Cv, acc);
    }
    red[tid] = acc;
    __syncthreads();
    for (int o = 128; o > 0; o >>= 1) {
        if (tid < o) red[tid] += red[tid + o];
        __syncthreads();
    }
    if (tid == 0) g_cpart[blockIdx.x] = red[0];
}

// 1 block x 1024 threads: deterministic reduce of 1024 partials per batch.
__global__ void costredk(float* __restrict__ cost) {
    __shared__ float red[1024];
    int tid = threadIdx.x;
    for (int b = 0; b < NB; b++) {
        red[tid] = g_cpart[b * 1024 + tid];
        __syncthreads();
        for (int o = 512; o > 0; o >>= 1) {
            if (tid < o) red[tid] += red[tid + o];
            __syncthreads();
        }
        if (tid == 0) cost[b] = red[0];
        __syncthreads();
    }
}

// ---------------- launch ---------------------------------------------------
extern "C" void kernel_launch(void* const* d_in, const int* in_sizes, int n_in,
                              void* d_out, int out_size) {
    const float* x = (const float*)d_in[0];   // [N,P1,D]
    const float* y = (const float*)d_in[1];   // [N,P2,D]
    const float* M = (const float*)d_in[2];   // [D,D]
    float* out  = (float*)d_out;              // cost[4] | pi[N*P*P] | C[N*P*P]
    float* cost = out;
    float* pi   = out + 4;
    float* C    = out + 4 + (size_t)NPITEMS;

    initk<<<1, 1024>>>(M);
    prepk<<<2 * NB * PP, 64>>>(x, y);
    dim3 cbg(PP / 64, PP / 64, NB);
    cbuildk<<<cbg, 256>>>(y, C);

    for (int it = 0; it < MAXIT; ++it) {
        ukern<<<NB * PP / 8, 256>>>(C);
        vkern<<<NB * (PP / 32), 512>>>(C, it);
    }

    fink<<<4096, 256>>>(C, pi);
    costredk<<<1, 1024>>>(cost);
}

// round 2
// speedup vs baseline: 1.1890x; 1.1890x over previous
#include <cuda_runtime.h>
#include <math.h>

// Problem constants: N=4, P1=P2=2048, D=64
#define NB 4
#define PP 2048
#define DD 64
#define EPSR     0.1f
#define INV_EPS  10.0f
#define THRESHV  0.1f
#define MAXIT    50
#define LOGMU    (-7.6245985f)   // log(1/2048 + 1e-8)
#define NBLK     128
#define NT       1024
#define NPITEMS  (NB * PP * PP)
#define MNEG     (-3.402823466e38f)

// ---------------- device scratch (no allocations allowed) ------------------
__device__ float g_XS[NB * PP * DD];     // x @ (M+M^T)
__device__ float g_dx[NB * PP];
__device__ float g_dy[NB * PP];
__device__ float g_u[NB * PP];
__device__ float g_v[NB * PP];
__device__ float g_duabs[NB * PP];
__device__ float g_cpart[NBLK];
__device__ unsigned g_bar_count;
__device__ volatile unsigned g_bar_gen;

// ---------------- software grid barrier (all NBLK blocks resident) ---------
__device__ __forceinline__ void grid_bar() {
    __syncthreads();
    if (threadIdx.x == 0) {
        __threadfence();                       // order my writes before arrive
        unsigned gen = g_bar_gen;              // read BEFORE arrive (no-deadlock)
        if (atomicAdd(&g_bar_count, 1u) == NBLK - 1) {
            g_bar_count = 0;
            __threadfence();
            g_bar_gen = gen + 1;               // release
        } else {
            while (g_bar_gen == gen) __nanosleep(64);
        }
        __threadfence();                       // gpu-scope fence -> L1 invalidate
    }
    __syncthreads();
}

// online-LSE merge with a single exp
__device__ __forceinline__ void lse_merge(float& m, float& s, float mc, float sc) {
    float mmax = fmaxf(m, mc);
    float e = __expf(fminf(m, mc) - mmax);
    s = (m >= mc) ? fmaf(sc, e, s) : fmaf(s, e, sc);
    m = mmax;
}

__global__ void __launch_bounds__(NT, 1)
sinkhorn_all(const float* __restrict__ x, const float* __restrict__ y,
             const float* __restrict__ Mm,
             float* __restrict__ cost, float* __restrict__ pi,
             float* __restrict__ C)
{
    __shared__ __align__(16) float sv[PP];      // v or u vector for this n (8KB)
    __shared__ __align__(16) float sa[4224];    // GEMM A / S / pm   (16.5KB)
    __shared__ __align__(16) float sb[4224];    // GEMM B / red / ps (16.5KB)

    const int t    = threadIdx.x;
    const int b    = blockIdx.x;
    const int lane = t & 31;
    const int w    = t >> 5;

    // ---- phase 0: zero u, v slice -----------------------------------------
    if (t < 64) {
        g_u[(b << 6) + t] = 0.0f;
        g_v[(b << 6) + t] = 0.0f;
    }

    // ---- phase 1: S = M + M^T into sa (every block; broadcast from L2) ----
    for (int idx = t; idx < DD * DD; idx += NT) {
        int d = idx >> 6, e = idx & 63;
        sa[idx] = Mm[idx] + Mm[(e << 6) + d];
    }
    __syncthreads();

    // ---- phase 2: prep -- XS = x@S, dx = xMx^T, dy = yMy^T ----------------
    // block b handles x rows [b*64, b*64+64) and the same y rows.
    for (int half = 0; half < 2; half++) {
        const float* src = half ? y : x;
        for (int batch = 0; batch < 4; batch++) {
            int row0 = (b << 6) + (batch << 4);          // 16 rows per batch
            __syncthreads();
            sb[t] = src[(size_t)row0 * DD + t];          // stage 16x64
            __syncthreads();
            int slot = t >> 6, e = t & 63;
            float acc = 0.0f;
            #pragma unroll 16
            for (int d = 0; d < DD; d++)
                acc = fmaf(sa[(d << 6) + e], sb[(slot << 6) + d], acc);
            int row = row0 + slot;
            if (!half) g_XS[(size_t)row * DD + e] = acc;
            sb[1024 + t] = acc * sb[(slot << 6) + e];
            __syncthreads();
            for (int off = 32; off > 0; off >>= 1) {
                if (e < off) sb[1024 + (slot << 6) + e] += sb[1024 + (slot << 6) + e + off];
                __syncthreads();
            }
            if (e == 0) {
                float dv = 0.5f * sb[1024 + (slot << 6)];   // x S x^T / 2 = x M x^T
                if (!half) g_dx[row] = dv; else g_dy[row] = dv;
            }
        }
    }

    grid_bar();   // XS/dx/dy complete chip-wide

    // ---- phase 3: C build. 128x128 tiles, K staged 32 at a time -----------
    for (int tt = 0; tt < 8; tt++) {
        int tile = b + (tt << 7);           // 0..1023
        int n  = tile >> 8;
        int rem = tile & 255;
        int i0 = (rem >> 4) << 7;
        int j0 = (rem & 15) << 7;
        float acc[16];
        #pragma unroll
        for (int q = 0; q < 16; q++) acc[q] = 0.0f;

        #pragma unroll
        for (int ks = 0; ks < 64; ks += 32) {
            __syncthreads();
            {
                int i = t >> 3, kq = t & 7;
                float4 xa = *(const float4*)(g_XS + (size_t)(n * PP + i0 + i) * DD + ks + (kq << 2));
                float4 yb = *(const float4*)(y    + (size_t)(n * PP + j0 + i) * DD + ks + (kq << 2));
                int k0 = kq << 2;
                sa[(k0+0)*132 + i] = xa.x;  sa[(k0+1)*132 + i] = xa.y;
                sa[(k0+2)*132 + i] = xa.z;  sa[(k0+3)*132 + i] = xa.w;
                sb[(k0+0)*132 + i] = yb.x;  sb[(k0+1)*132 + i] = yb.y;
                sb[(k0+2)*132 + i] = yb.z;  sb[(k0+3)*132 + i] = yb.w;
            }
            __syncthreads();
            int cx = t & 31, cy = t >> 5;
            #pragma unroll
            for (int k = 0; k < 32; k++) {
                float4 a4 = *(const float4*)&sa[k*132 + (cy << 2)];
                float4 b4 = *(const float4*)&sb[k*132 + (cx << 2)];
                acc[ 0] = fmaf(a4.x, b4.x, acc[ 0]);
                acc[ 1] = fmaf(a4.x, b4.y, acc[ 1]);
                acc[ 2] = fmaf(a4.x, b4.z, acc[ 2]);
                acc[ 3] = fmaf(a4.x, b4.w, acc[ 3]);
                acc[ 4] = fmaf(a4.y, b4.x, acc[ 4]);
                acc[ 5] = fmaf(a4.y, b4.y, acc[ 5]);
                acc[ 6] = fmaf(a4.y, b4.z, acc[ 6]);
                acc[ 7] = fmaf(a4.y, b4.w, acc[ 7]);
                acc[ 8] = fmaf(a4.z, b4.x, acc[ 8]);
                acc[ 9] = fmaf(a4.z, b4.y, acc[ 9]);
                acc[10] = fmaf(a4.z, b4.z, acc[10]);
                acc[11] = fmaf(a4.z, b4.w, acc[11]);
                acc[12] = fmaf(a4.w, b4.x, acc[12]);
                acc[13] = fmaf(a4.w, b4.y, acc[13]);
                acc[14] = fmaf(a4.w, b4.z, acc[14]);
                acc[15] = fmaf(a4.w, b4.w, acc[15]);
            }
        }
        int cx = t & 31, cy = t >> 5;
        float dxr[4], dyr[4];
        #pragma unroll
        for (int q = 0; q < 4; q++) {
            dxr[q] = g_dx[n * PP + i0 + (cy << 2) + q];
            dyr[q] = g_dy[n * PP + j0 + (cx << 2) + q];
        }
        #pragma unroll
        for (int a = 0; a < 4; a++) {
            float4 o;
            o.x = dxr[a] + dyr[0] - acc[(a << 2) + 0];
            o.y = dxr[a] + dyr[1] - acc[(a << 2) + 1];
            o.z = dxr[a] + dyr[2] - acc[(a << 2) + 2];
            o.w = dxr[a] + dyr[3] - acc[(a << 2) + 3];
            *(float4*)(C + (size_t)(n * PP + i0 + (cy << 2) + a) * PP + j0 + (cx << 2)) = o;
        }
    }

    grid_bar();   // C complete chip-wide (u=v=0 also visible)

    // ---- phase 4: Sinkhorn iterations -------------------------------------
    const int n_pass = b >> 5;          // batch index for passes
    const int sub    = b & 31;          // 64-row / 64-col sub-block within n
    const float4* C4n = (const float4*)C + (size_t)n_pass * PP * (PP >> 2);
    bool active = true;

    for (int it = 0; it < MAXIT; it++) {
        // ===== U pass: row LSE of (v_j - C_ij)/eps, one warp per row =======
        sv[t]        = g_v[(n_pass << 11) + t];
        sv[t + 1024] = g_v[(n_pass << 11) + 1024 + t];
        __syncthreads();
        {
            const float4* vs4 = (const float4*)sv;
            #pragma unroll
            for (int rep = 0; rep < 2; rep++) {
                int row = (sub << 6) + (rep << 5) + w;      // local row
                const float4* Cr = C4n + (size_t)row * (PP >> 2);
                float m = MNEG, s = 0.0f;
                #pragma unroll
                for (int c8 = 0; c8 < 8; c8++) {
                    float4 a  = Cr[lane + (c8 << 6)];
                    float4 bb = Cr[lane + 32 + (c8 << 6)];
                    float4 va = vs4[lane + (c8 << 6)];
                    float4 vb = vs4[lane + 32 + (c8 << 6)];
                    float z0 = (va.x - a.x)  * INV_EPS;
                    float z1 = (va.y - a.y)  * INV_EPS;
                    float z2 = (va.z - a.z)  * INV_EPS;
                    float z3 = (va.w - a.w)  * INV_EPS;
                    float z4 = (vb.x - bb.x) * INV_EPS;
                    float z5 = (vb.y - bb.y) * INV_EPS;
                    float z6 = (vb.z - bb.z) * INV_EPS;
                    float z7 = (vb.w - bb.w) * INV_EPS;
                    float mc = fmaxf(fmaxf(fmaxf(z0, z1), fmaxf(z2, z3)),
                                     fmaxf(fmaxf(z4, z5), fmaxf(z6, z7)));
                    float sc = __expf(z0 - mc) + __expf(z1 - mc)
                             + __expf(z2 - mc) + __expf(z3 - mc)
                             + __expf(z4 - mc) + __expf(z5 - mc)
                             + __expf(z6 - mc) + __expf(z7 - mc);
                    lse_merge(m, s, mc, sc);
                }
                #pragma unroll
                for (int off = 16; off > 0; off >>= 1) {
                    float mo = __shfl_xor_sync(0xffffffffu, m, off);
                    float so = __shfl_xor_sync(0xffffffffu, s, off);
                    lse_merge(m, s, mo, so);
                }
                if (lane == 0) {
                    float lse  = m + logf(s);
                    float unew = EPSR * (LOGMU - lse);
                    int gr = (n_pass << 11) + row;
                    g_duabs[gr] = fabsf(unew - g_u[gr]);
                    g_u[gr] = unew;
                }
            }
        }
        grid_bar();

        // ===== V pass: column LSE of (u_i - C_ij)/eps ======================
        sv[t]        = g_u[(n_pass << 11) + t];
        sv[t + 1024] = g_u[(n_pass << 11) + 1024 + t];
        __syncthreads();
        {
            int cg  = t & 15;            // float4 column group within 64 cols
            int seg = t >> 4;            // 64 row-segments of 32 rows
            int j0  = sub << 6;
            const float4* Cc = C4n + (j0 >> 2) + cg;
            float m0 = MNEG, m1 = MNEG, m2 = MNEG, m3 = MNEG;
            float s0 = 0.f, s1 = 0.f, s2 = 0.f, s3 = 0.f;
            int ib = seg << 5;
            #pragma unroll 2
            for (int ch = 0; ch < 8; ch++) {
                int ir = ib + (ch << 2);
                float4 r0 = Cc[(size_t)(ir + 0) * 512];
                float4 r1 = Cc[(size_t)(ir + 1) * 512];
                float4 r2 = Cc[(size_t)(ir + 2) * 512];
                float4 r3 = Cc[(size_t)(ir + 3) * 512];
                float u0 = sv[ir], u1 = sv[ir + 1], u2 = sv[ir + 2], u3 = sv[ir + 3];
                // column 0
                {
                    float za = (u0 - r0.x) * INV_EPS, zb2 = (u1 - r1.x) * INV_EPS;
                    float zc = (u2 - r2.x) * INV_EPS, zd = (u3 - r3.x) * INV_EPS;
                    float mc = fmaxf(fmaxf(za, zb2), fmaxf(zc, zd));
                    float sc = __expf(za - mc) + __expf(zb2 - mc) + __expf(zc - mc) + __expf(zd - mc);
                    lse_merge(m0, s0, mc, sc);
                }
                // column 1
                {
                    float za = (u0 - r0.y) * INV_EPS, zb2 = (u1 - r1.y) * INV_EPS;
                    float zc = (u2 - r2.y) * INV_EPS, zd = (u3 - r3.y) * INV_EPS;
                    float mc = fmaxf(fmaxf(za, zb2), fmaxf(zc, zd));
                    float sc = __expf(za - mc) + __expf(zb2 - mc) + __expf(zc - mc) + __expf(zd - mc);
                    lse_merge(m1, s1, mc, sc);
                }
                // column 2
                {
                    float za = (u0 - r0.z) * INV_EPS, zb2 = (u1 - r1.z) * INV_EPS;
                    float zc = (u2 - r2.z) * INV_EPS, zd = (u3 - r3.z) * INV_EPS;
                    float mc = fmaxf(fmaxf(za, zb2), fmaxf(zc, zd));
                    float sc = __expf(za - mc) + __expf(zb2 - mc) + __expf(zc - mc) + __expf(zd - mc);
                    lse_merge(m2, s2, mc, sc);
                }
                // column 3
                {
                    float za = (u0 - r0.w) * INV_EPS, zb2 = (u1 - r1.w) * INV_EPS;
                    float zc = (u2 - r2.w) * INV_EPS, zd = (u3 - r3.w) * INV_EPS;
                    float mc = fmaxf(fmaxf(za, zb2), fmaxf(zc, zd));
                    float sc = __expf(za - mc) + __expf(zb2 - mc) + __expf(zc - mc) + __expf(zd - mc);
                    lse_merge(m3, s3, mc, sc);
                }
            }
            sa[(seg << 6) + (cg << 2) + 0] = m0;  sb[(seg << 6) + (cg << 2) + 0] = s0;
            sa[(seg << 6) + (cg << 2) + 1] = m1;  sb[(seg << 6) + (cg << 2) + 1] = s1;
            sa[(seg << 6) + (cg << 2) + 2] = m2;  sb[(seg << 6) + (cg << 2) + 2] = s2;
            sa[(seg << 6) + (cg << 2) + 3] = m3;  sb[(seg << 6) + (cg << 2) + 3] = s3;
            __syncthreads();
            // stage 1: 64 segs -> 8
            float mm = MNEG, ss = 0.0f;
            int col = t & 63, sg = t >> 6;   // sg 0..15, only sg<8 active
            if (sg < 8) {
                #pragma unroll
                for (int r = 0; r < 8; r++)
                    lse_merge(mm, ss, sa[((sg << 3) + r) * 64 + col], sb[((sg << 3) + r) * 64 + col]);
            }
            __syncthreads();
            if (sg < 8) { sa[(sg << 6) + col] = mm; sb[(sg << 6) + col] = ss; }
            __syncthreads();
            // stage 2: 8 -> 1, write v
            if (t < 64) {
                float M2 = MNEG, S2 = 0.0f;
                #pragma unroll
                for (int r = 0; r < 8; r++)
                    lse_merge(M2, S2, sa[(r << 6) + t], sb[(r << 6) + t]);
                float lse = M2 + logf(S2);
                g_v[(n_pass << 11) + j0 + t] = EPSR * (LOGMU - lse);
            }
            __syncthreads();
        }

        // ===== convergence check: replicated deterministic reduction =======
        {
            float ea = 0.0f;
            #pragma unroll
            for (int q = 0; q < 8; q++) ea += g_duabs[t + (q << 10)];
            sb[t] = ea;
            __syncthreads();
            for (int off = 512; off > 0; off >>= 1) {
                if (t < off) sb[t] += sb[t + off];
                __syncthreads();
            }
            active = (sb[0] * 0.25f >= THRESHV);   // err = total/NB
            __syncthreads();
        }
        grid_bar();
        if (!active) break;
    }

    // ---- phase 5: pi = exp((-C+u+v)/eps), cost partials --------------------
    {
        sv[t]        = g_v[(n_pass << 11) + t];
        sv[t + 1024] = g_v[(n_pass << 11) + 1024 + t];
        if (t < 64) sa[t] = g_u[(n_pass << 11) + (sub << 6) + t];
        __syncthreads();
        const float4* vs4 = (const float4*)sv;
        const float4* Cb4 = C4n + (size_t)(sub << 6) * 512;
        float4* pi4 = (float4*)pi + (size_t)(n_pass * PP + (sub << 6)) * 512;
        float accc = 0.0f;
        #pragma unroll 4
        for (int k2 = 0; k2 < 32; k2++) {
            int idx = t + (k2 << 10);
            int row = idx >> 9;
            int c4  = idx & 511;
            float4 cc = Cb4[(size_t)row * 512 + c4];
            float  uu = sa[row];
            float4 vv = vs4[c4];
            float p0 = __expf((uu + vv.x - cc.x) * INV_EPS);
            float p1 = __expf((uu + vv.y - cc.y) * INV_EPS);
            float p2 = __expf((uu + vv.z - cc.z) * INV_EPS);
            float p3 = __expf((uu + vv.w - cc.w) * INV_EPS);
            float4 po; po.x = p0; po.y = p1; po.z = p2; po.w = p3;
            pi4[(size_t)row * 512 + c4] = po;
            accc = fmaf(p0, cc.x, accc);
            accc = fmaf(p1, cc.y, accc);
            accc = fmaf(p2, cc.z, accc);
            accc = fmaf(p3, cc.w, accc);
        }
        __syncthreads();
        sb[t] = accc;
        __syncthreads();
        for (int off = 512; off > 0; off >>= 1) {
            if (t < off) sb[t] += sb[t + off];
            __syncthreads();
        }
        if (t == 0) g_cpart[b] = sb[0];
    }
    grid_bar();
    if (b == 0 && t == 0) {
        #pragma unroll
        for (int n = 0; n < NB; n++) {
            float c = 0.0f;
            for (int q = 0; q < 32; q++) c += g_cpart[(n << 5) + q];
            cost[n] = c;
        }
    }
}

// ---------------- launch ---------------------------------------------------
extern "C" void kernel_launch(void* const* d_in, const int* in_sizes, int n_in,
                              void* d_out, int out_size) {
    const float* x = (const float*)d_in[0];   // [N,P1,D]
    const float* y = (const float*)d_in[1];   // [N,P2,D]
    const float* M = (const float*)d_in[2];   // [D,D]
    float* out  = (float*)d_out;              // cost[4] | pi | C
    float* cost = out;
    float* pi   = out + 4;
    float* C    = out + 4 + (size_t)NPITEMS;

    sinkhorn_all<<<NBLK, NT>>>(x, y, M, cost, pi, C);
}

// round 3
// speedup vs baseline: 1.3257x; 1.1150x over previous
#include <cuda_runtime.h>
#include <math.h>

// Problem constants: N=4, P1=P2=2048, D=64
#define NB 4
#define PP 2048
#define DD 64
#define EPSR     0.1f
#define INV_EPS  10.0f
#define SCL      14.426950408889634f   // INV_EPS * log2(e)
#define ELN2     0.0693147180559945f   // EPSR * ln(2)
#define UC0      (-0.76245985f)        // EPSR * LOGMU
#define THRESHV  0.1f
#define MAXIT    50
#define NBLK     128
#define NT       1024
#define NPITEMS  (NB * PP * PP)
#define MNEG     (-3.402823466e38f)

// ---------------- device scratch (no allocations allowed) ------------------
__device__ float g_XS[NB * PP * DD];     // x @ (M+M^T)
__device__ float g_dx[NB * PP];
__device__ float g_dy[NB * PP];
__device__ float g_u[NB * PP];
__device__ float g_v[NB * PP];
__device__ float g_duabs[NB * PP];
__device__ float g_cpart[NBLK];
__device__ unsigned g_bar_count;
__device__ volatile unsigned g_bar_gen;

__device__ __forceinline__ float ex2f(float x) {
    float r;
    asm("ex2.approx.ftz.f32 %0, %1;" : "=f"(r) : "f"(x));
    return r;
}

// online-LSE merge in log2 domain, single ex2
__device__ __forceinline__ void lse_merge2(float& m, float& s, float mc, float sc) {
    float mmax = fmaxf(m, mc);
    float e = ex2f(fminf(m, mc) - mmax);
    s = (m >= mc) ? fmaf(sc, e, s) : fmaf(s, e, sc);
    m = mmax;
}

// ---------------- software grid barrier (all NBLK blocks resident) ---------
__device__ __forceinline__ void grid_bar() {
    __syncthreads();
    if (threadIdx.x == 0) {
        __threadfence();
        unsigned gen = g_bar_gen;
        if (atomicAdd(&g_bar_count, 1u) == NBLK - 1) {
            g_bar_count = 0;
            __threadfence();
            g_bar_gen = gen + 1;
        } else {
            while (g_bar_gen == gen) __nanosleep(32);
        }
        __threadfence();
    }
    __syncthreads();
}

__global__ void __launch_bounds__(NT, 1)
sinkhorn_all(const float* __restrict__ x, const float* __restrict__ y,
             const float* __restrict__ Mm,
             float* __restrict__ cost, float* __restrict__ pi,
             float* __restrict__ C)
{
    __shared__ __align__(16) float sv[PP];      // scaled u/v vector (8KB)
    __shared__ __align__(16) float sa[4224];
    __shared__ __align__(16) float sb[4224];

    const int t    = threadIdx.x;
    const int b    = blockIdx.x;
    const int lane = t & 31;
    const int w    = t >> 5;

    // ---- phase 0: zero u, v slice -----------------------------------------
    if (t < 64) {
        g_u[(b << 6) + t] = 0.0f;
        g_v[(b << 6) + t] = 0.0f;
    }

    // ---- phase 1: S = M + M^T ---------------------------------------------
    for (int idx = t; idx < DD * DD; idx += NT) {
        int d = idx >> 6, e = idx & 63;
        sa[idx] = Mm[idx] + Mm[(e << 6) + d];
    }
    __syncthreads();

    // ---- phase 2: XS = x@S, dx = xMx^T, dy = yMy^T ------------------------
    for (int half = 0; half < 2; half++) {
        const float* src = half ? y : x;
        for (int batch = 0; batch < 4; batch++) {
            int row0 = (b << 6) + (batch << 4);
            __syncthreads();
            sb[t] = src[(size_t)row0 * DD + t];
            __syncthreads();
            int slot = t >> 6, e = t & 63;
            float acc = 0.0f;
            #pragma unroll 16
            for (int d = 0; d < DD; d++)
                acc = fmaf(sa[(d << 6) + e], sb[(slot << 6) + d], acc);
            int row = row0 + slot;
            if (!half) g_XS[(size_t)row * DD + e] = acc;
            sb[1024 + t] = acc * sb[(slot << 6) + e];
            __syncthreads();
            for (int off = 32; off > 0; off >>= 1) {
                if (e < off) sb[1024 + (slot << 6) + e] += sb[1024 + (slot << 6) + e + off];
                __syncthreads();
            }
            if (e == 0) {
                float dv = 0.5f * sb[1024 + (slot << 6)];
                if (!half) g_dx[row] = dv; else g_dy[row] = dv;
            }
        }
    }

    grid_bar();

    // ---- phase 3: C build. 128x128 tiles ----------------------------------
    for (int tt = 0; tt < 8; tt++) {
        int tile = b + (tt << 7);
        int n  = tile >> 8;
        int rem = tile & 255;
        int i0 = (rem >> 4) << 7;
        int j0 = (rem & 15) << 7;
        float acc[16];
        #pragma unroll
        for (int q = 0; q < 16; q++) acc[q] = 0.0f;

        #pragma unroll
        for (int ks = 0; ks < 64; ks += 32) {
            __syncthreads();
            {
                int i = t >> 3, kq = t & 7;
                float4 xa = *(const float4*)(g_XS + (size_t)(n * PP + i0 + i) * DD + ks + (kq << 2));
                float4 yb = *(const float4*)(y    + (size_t)(n * PP + j0 + i) * DD + ks + (kq << 2));
                int k0 = kq << 2;
                sa[(k0+0)*132 + i] = xa.x;  sa[(k0+1)*132 + i] = xa.y;
                sa[(k0+2)*132 + i] = xa.z;  sa[(k0+3)*132 + i] = xa.w;
                sb[(k0+0)*132 + i] = yb.x;  sb[(k0+1)*132 + i] = yb.y;
                sb[(k0+2)*132 + i] = yb.z;  sb[(k0+3)*132 + i] = yb.w;
            }
            __syncthreads();
            int cx = t & 31, cy = t >> 5;
            #pragma unroll
            for (int k = 0; k < 32; k++) {
                float4 a4 = *(const float4*)&sa[k*132 + (cy << 2)];
                float4 b4 = *(const float4*)&sb[k*132 + (cx << 2)];
                acc[ 0] = fmaf(a4.x, b4.x, acc[ 0]);
                acc[ 1] = fmaf(a4.x, b4.y, acc[ 1]);
                acc[ 2] = fmaf(a4.x, b4.z, acc[ 2]);
                acc[ 3] = fmaf(a4.x, b4.w, acc[ 3]);
                acc[ 4] = fmaf(a4.y, b4.x, acc[ 4]);
                acc[ 5] = fmaf(a4.y, b4.y, acc[ 5]);
                acc[ 6] = fmaf(a4.y, b4.z, acc[ 6]);
                acc[ 7] = fmaf(a4.y, b4.w, acc[ 7]);
                acc[ 8] = fmaf(a4.z, b4.x, acc[ 8]);
                acc[ 9] = fmaf(a4.z, b4.y, acc[ 9]);
                acc[10] = fmaf(a4.z, b4.z, acc[10]);
                acc[11] = fmaf(a4.z, b4.w, acc[11]);
                acc[12] = fmaf(a4.w, b4.x, acc[12]);
                acc[13] = fmaf(a4.w, b4.y, acc[13]);
                acc[14] = fmaf(a4.w, b4.z, acc[14]);
                acc[15] = fmaf(a4.w, b4.w, acc[15]);
            }
        }
        int cx = t & 31, cy = t >> 5;
        float dxr[4], dyr[4];
        #pragma unroll
        for (int q = 0; q < 4; q++) {
            dxr[q] = g_dx[n * PP + i0 + (cy << 2) + q];
            dyr[q] = g_dy[n * PP + j0 + (cx << 2) + q];
        }
        #pragma unroll
        for (int a = 0; a < 4; a++) {
            float4 o;
            o.x = dxr[a] + dyr[0] - acc[(a << 2) + 0];
            o.y = dxr[a] + dyr[1] - acc[(a << 2) + 1];
            o.z = dxr[a] + dyr[2] - acc[(a << 2) + 2];
            o.w = dxr[a] + dyr[3] - acc[(a << 2) + 3];
            *(float4*)(C + (size_t)(n * PP + i0 + (cy << 2) + a) * PP + j0 + (cx << 2)) = o;
        }
    }

    grid_bar();

    // ---- phase 4: Sinkhorn iterations -------------------------------------
    const int n_pass = b >> 5;
    const int sub    = b & 31;
    const float4* C4n = (const float4*)C + (size_t)n_pass * PP * (PP >> 2);
    bool active = true;

    for (int it = 0; it < MAXIT; it++) {
        // ===== U pass: row LSE, one warp per row, double-buffered ==========
        sv[t]        = g_v[(n_pass << 11) + t] * SCL;
        sv[t + 1024] = g_v[(n_pass << 11) + 1024 + t] * SCL;
        __syncthreads();
        {
            const float4* vs4 = (const float4*)sv;
            #pragma unroll
            for (int rep = 0; rep < 2; rep++) {
                int row = (sub << 6) + (rep << 5) + w;
                const float4* Cr = C4n + (size_t)row * 512;
                float4 ca = Cr[lane];
                float4 cb = Cr[lane + 32];
                float m = MNEG, s = 0.0f;
                #pragma unroll
                for (int c = 0; c < 8; c++) {
                    float4 na, nb;
                    if (c < 7) {
                        na = Cr[lane + (c << 6) + 64];
                        nb = Cr[lane + (c << 6) + 96];
                    }
                    float4 va = vs4[lane + (c << 6)];
                    float4 vb = vs4[lane + (c << 6) + 32];
                    float z0 = fmaf(ca.x, -SCL, va.x);
                    float z1 = fmaf(ca.y, -SCL, va.y);
                    float z2 = fmaf(ca.z, -SCL, va.z);
                    float z3 = fmaf(ca.w, -SCL, va.w);
                    float z4 = fmaf(cb.x, -SCL, vb.x);
                    float z5 = fmaf(cb.y, -SCL, vb.y);
                    float z6 = fmaf(cb.z, -SCL, vb.z);
                    float z7 = fmaf(cb.w, -SCL, vb.w);
                    float mc = fmaxf(fmaxf(fmaxf(z0, z1), fmaxf(z2, z3)),
                                     fmaxf(fmaxf(z4, z5), fmaxf(z6, z7)));
                    float sc = ex2f(z0 - mc) + ex2f(z1 - mc)
                             + ex2f(z2 - mc) + ex2f(z3 - mc)
                             + ex2f(z4 - mc) + ex2f(z5 - mc)
                             + ex2f(z6 - mc) + ex2f(z7 - mc);
                    lse_merge2(m, s, mc, sc);
                    ca = na; cb = nb;
                }
                #pragma unroll
                for (int off = 16; off > 0; off >>= 1) {
                    float mo = __shfl_xor_sync(0xffffffffu, m, off);
                    float so = __shfl_xor_sync(0xffffffffu, s, off);
                    lse_merge2(m, s, mo, so);
                }
                if (lane == 0) {
                    float unew = UC0 - ELN2 * (m + log2f(s));
                    int gr = (n_pass << 11) + row;
                    g_duabs[gr] = fabsf(unew - g_u[gr]);
                    g_u[gr] = unew;
                }
            }
        }
        grid_bar();

        // ===== V pass: column LSE, double-buffered =========================
        sv[t]        = g_u[(n_pass << 11) + t] * SCL;
        sv[t + 1024] = g_u[(n_pass << 11) + 1024 + t] * SCL;
        __syncthreads();
        {
            int cg  = t & 15;
            int seg = t >> 4;
            int j0  = sub << 6;
            const float4* Cc = C4n + (j0 >> 2) + cg;
            int ib = seg << 5;
            float m0 = MNEG, m1 = MNEG, m2 = MNEG, m3 = MNEG;
            float s0 = 0.f, s1 = 0.f, s2 = 0.f, s3 = 0.f;
            float4 r0 = Cc[(size_t)(ib + 0) * 512];
            float4 r1 = Cc[(size_t)(ib + 1) * 512];
            float4 r2 = Cc[(size_t)(ib + 2) * 512];
            float4 r3 = Cc[(size_t)(ib + 3) * 512];
            #pragma unroll
            for (int ch = 0; ch < 8; ch++) {
                int ir = ib + (ch << 2);
                float4 n0, n1, n2, n3;
                if (ch < 7) {
                    n0 = Cc[(size_t)(ir + 4) * 512];
                    n1 = Cc[(size_t)(ir + 5) * 512];
                    n2 = Cc[(size_t)(ir + 6) * 512];
                    n3 = Cc[(size_t)(ir + 7) * 512];
                }
                float u0 = sv[ir], u1 = sv[ir + 1], u2 = sv[ir + 2], u3 = sv[ir + 3];
                {
                    float za = fmaf(r0.x, -SCL, u0), zb = fmaf(r1.x, -SCL, u1);
                    float zc = fmaf(r2.x, -SCL, u2), zd = fmaf(r3.x, -SCL, u3);
                    float mc = fmaxf(fmaxf(za, zb), fmaxf(zc, zd));
                    float sc = ex2f(za - mc) + ex2f(zb - mc) + ex2f(zc - mc) + ex2f(zd - mc);
                    lse_merge2(m0, s0, mc, sc);
                }
                {
                    float za = fmaf(r0.y, -SCL, u0), zb = fmaf(r1.y, -SCL, u1);
                    float zc = fmaf(r2.y, -SCL, u2), zd = fmaf(r3.y, -SCL, u3);
                    float mc = fmaxf(fmaxf(za, zb), fmaxf(zc, zd));
                    float sc = ex2f(za - mc) + ex2f(zb - mc) + ex2f(zc - mc) + ex2f(zd - mc);
                    lse_merge2(m1, s1, mc, sc);
                }
                {
                    float za = fmaf(r0.z, -SCL, u0), zb = fmaf(r1.z, -SCL, u1);
                    float zc = fmaf(r2.z, -SCL, u2), zd = fmaf(r3.z, -SCL, u3);
                    float mc = fmaxf(fmaxf(za, zb), fmaxf(zc, zd));
                    float sc = ex2f(za - mc) + ex2f(zb - mc) + ex2f(zc - mc) + ex2f(zd - mc);
                    lse_merge2(m2, s2, mc, sc);
                }
                {
                    float za = fmaf(r0.w, -SCL, u0), zb = fmaf(r1.w, -SCL, u1);
                    float zc = fmaf(r2.w, -SCL, u2), zd = fmaf(r3.w, -SCL, u3);
                    float mc = fmaxf(fmaxf(za, zb), fmaxf(zc, zd));
                    float sc = ex2f(za - mc) + ex2f(zb - mc) + ex2f(zc - mc) + ex2f(zd - mc);
                    lse_merge2(m3, s3, mc, sc);
                }
                r0 = n0; r1 = n1; r2 = n2; r3 = n3;
            }
            sa[(seg << 6) + (cg << 2) + 0] = m0;  sb[(seg << 6) + (cg << 2) + 0] = s0;
            sa[(seg << 6) + (cg << 2) + 1] = m1;  sb[(seg << 6) + (cg << 2) + 1] = s1;
            sa[(seg << 6) + (cg << 2) + 2] = m2;  sb[(seg << 6) + (cg << 2) + 2] = s2;
            sa[(seg << 6) + (cg << 2) + 3] = m3;  sb[(seg << 6) + (cg << 2) + 3] = s3;
            __syncthreads();
            float mm = MNEG, ss = 0.0f;
            int col = t & 63, sg = t >> 6;
            if (sg < 8) {
                #pragma unroll
                for (int r = 0; r < 8; r++)
                    lse_merge2(mm, ss, sa[((sg << 3) + r) * 64 + col], sb[((sg << 3) + r) * 64 + col]);
            }
            __syncthreads();
            if (sg < 8) { sa[(sg << 6) + col] = mm; sb[(sg << 6) + col] = ss; }
            __syncthreads();
            if (t < 64) {
                float M2 = MNEG, S2 = 0.0f;
                #pragma unroll
                for (int r = 0; r < 8; r++)
                    lse_merge2(M2, S2, sa[(r << 6) + t], sb[(r << 6) + t]);
                g_v[(n_pass << 11) + j0 + t] = UC0 - ELN2 * (M2 + log2f(S2));
            }
            __syncthreads();
        }

        // ===== convergence: replicated deterministic reduction =============
        {
            float ea = 0.0f;
            #pragma unroll
            for (int q = 0; q < 8; q++) ea += g_duabs[t + (q << 10)];
            sb[t] = ea;
            __syncthreads();
            for (int off = 512; off > 0; off >>= 1) {
                if (t < off) sb[t] += sb[t + off];
                __syncthreads();
            }
            active = (sb[0] * 0.25f >= THRESHV);
            __syncthreads();
        }
        grid_bar();
        if (!active) break;
    }

    // ---- phase 5: pi = exp2((u2+v2-C*SCL)), cost partials ------------------
    {
        sv[t]        = g_v[(n_pass << 11) + t] * SCL;
        sv[t + 1024] = g_v[(n_pass << 11) + 1024 + t] * SCL;
        if (t < 64) sa[t] = g_u[(n_pass << 11) + (sub << 6) + t] * SCL;
        __syncthreads();
        const float4* vs4 = (const float4*)sv;
        const float4* Cb4 = C4n + (size_t)(sub << 6) * 512;
        float4* pi4 = (float4*)pi + (size_t)(n_pass * PP + (sub << 6)) * 512;
        float accc = 0.0f;
        #pragma unroll 4
        for (int k2 = 0; k2 < 32; k2++) {
            int idx = t + (k2 << 10);
            int row = idx >> 9;
            int c4  = idx & 511;
            float4 cc = Cb4[(size_t)row * 512 + c4];
            float  uu = sa[row];
            float4 vv = vs4[c4];
            float p0 = ex2f(fmaf(cc.x, -SCL, uu + vv.x));
            float p1 = ex2f(fmaf(cc.y, -SCL, uu + vv.y));
            float p2 = ex2f(fmaf(cc.z, -SCL, uu + vv.z));
            float p3 = ex2f(fmaf(cc.w, -SCL, uu + vv.w));
            float4 po; po.x = p0; po.y = p1; po.z = p2; po.w = p3;
            pi4[(size_t)row * 512 + c4] = po;
            accc = fmaf(p0, cc.x, accc);
            accc = fmaf(p1, cc.y, accc);
            accc = fmaf(p2, cc.z, accc);
            accc = fmaf(p3, cc.w, accc);
        }
        __syncthreads();
        sb[t] = accc;
        __syncthreads();
        for (int off = 512; off > 0; off >>= 1) {
            if (t < off) sb[t] += sb[t + off];
            __syncthreads();
        }
        if (t == 0) g_cpart[b] = sb[0];
    }
    grid_bar();
    if (b == 0 && t == 0) {
        #pragma unroll
        for (int n = 0; n < NB; n++) {
            float c = 0.0f;
            for (int q = 0; q < 32; q++) c += g_cpart[(n << 5) + q];
            cost[n] = c;
        }
    }
}

// ---------------- launch ---------------------------------------------------
extern "C" void kernel_launch(void* const* d_in, const int* in_sizes, int n_in,
                              void* d_out, int out_size) {
    const float* x = (const float*)d_in[0];   // [N,P1,D]
    const float* y = (const float*)d_in[1];   // [N,P2,D]
    const float* M = (const float*)d_in[2];   // [D,D]
    float* out  = (float*)d_out;              // cost[4] | pi | C
    float* cost = out;
    float* pi   = out + 4;
    float* C    = out + 4 + (size_t)NPITEMS;

    sinkhorn_all<<<NBLK, NT>>>(x, y, M, cost, pi, C);
}

// round 4
// speedup vs baseline: 1.5510x; 1.1699x over previous
#include <cuda_runtime.h>
#include <math.h>

// Problem constants: N=4, P1=P2=2048, D=64
#define NB 4
#define PP 2048
#define DD 64
#define EPSR     0.1f
#define INV_EPS  10.0f
#define SCL      14.426950408889634f   // INV_EPS * log2(e)
#define ELN2     0.0693147180559945f   // EPSR * ln(2)
#define UC0      (-0.76245985f)        // EPSR * LOGMU
#define THRESHV  0.1f
#define MAXIT    50
#define NBLK     128
#define NT       1024
#define NPITEMS  (NB * PP * PP)
#define MNEG     (-3.402823466e38f)

// ---------------- device scratch (no allocations allowed) ------------------
__device__ float g_XS[NB * PP * DD];     // x @ (M+M^T)
__device__ float g_dx[NB * PP];
__device__ float g_dy[NB * PP];
__device__ float g_u[NB * PP];
__device__ float g_v[NB * PP];
__device__ float g_duabs[NB * PP];
__device__ float g_pm[NBLK * PP];        // per-block column LSE partial max
__device__ float g_ps[NBLK * PP];        // per-block column LSE partial sum
__device__ float g_cpart[NBLK];
__device__ unsigned g_bar_count;
__device__ volatile unsigned g_bar_gen;

__device__ __forceinline__ float ex2f(float x) {
    float r;
    asm("ex2.approx.ftz.f32 %0, %1;" : "=f"(r) : "f"(x));
    return r;
}

// online-LSE merge in log2 domain, single ex2
__device__ __forceinline__ void lse_merge2(float& m, float& s, float mc, float sc) {
    float mmax = fmaxf(m, mc);
    float e = ex2f(fminf(m, mc) - mmax);
    s = (m >= mc) ? fmaf(sc, e, s) : fmaf(s, e, sc);
    m = mmax;
}

// ---------------- software grid barrier (all NBLK blocks resident) ---------
__device__ __forceinline__ void grid_bar() {
    __syncthreads();
    if (threadIdx.x == 0) {
        __threadfence();
        unsigned gen = g_bar_gen;
        if (atomicAdd(&g_bar_count, 1u) == NBLK - 1) {
            g_bar_count = 0;
            __threadfence();
            g_bar_gen = gen + 1;
        } else {
            while (g_bar_gen == gen) __nanosleep(32);
        }
        __threadfence();
    }
    __syncthreads();
}

__global__ void __launch_bounds__(NT, 1)
sinkhorn_all(const float* __restrict__ x, const float* __restrict__ y,
             const float* __restrict__ Mm,
             float* __restrict__ cost, float* __restrict__ pi,
             float* __restrict__ C)
{
    __shared__ __align__(16) float sv[PP];      // scaled v (or u/v staging) 8KB
    __shared__ __align__(16) float sa[4224];    // cbuild A / fin staging
    __shared__ __align__(16) float sb[4224];    // cbuild B / reductions
    __shared__ float su[16];                    // scaled u_new for band
    __shared__ float pm2m[32], pm2s[32];        // per-warp row partials
    __shared__ float s_err[1];

    const int t    = threadIdx.x;
    const int b    = blockIdx.x;
    const int lane = t & 31;
    const int w    = t >> 5;

    // ---- phase 0: zero u, v slice -----------------------------------------
    if (t < 64) {
        g_u[(b << 6) + t] = 0.0f;
        g_v[(b << 6) + t] = 0.0f;
    }

    // ---- phase 1: S = M + M^T ---------------------------------------------
    for (int idx = t; idx < DD * DD; idx += NT) {
        int d = idx >> 6, e = idx & 63;
        sa[idx] = Mm[idx] + Mm[(e << 6) + d];
    }
    __syncthreads();

    // ---- phase 2: XS = x@S, dx = xMx^T, dy = yMy^T ------------------------
    for (int half = 0; half < 2; half++) {
        const float* src = half ? y : x;
        for (int batch = 0; batch < 4; batch++) {
            int row0 = (b << 6) + (batch << 4);
            __syncthreads();
            sb[t] = src[(size_t)row0 * DD + t];
            __syncthreads();
            int slot = t >> 6, e = t & 63;
            float acc = 0.0f;
            #pragma unroll 16
            for (int d = 0; d < DD; d++)
                acc = fmaf(sa[(d << 6) + e], sb[(slot << 6) + d], acc);
            int row = row0 + slot;
            if (!half) g_XS[(size_t)row * DD + e] = acc;
            sb[1024 + t] = acc * sb[(slot << 6) + e];
            __syncthreads();
            for (int off = 32; off > 0; off >>= 1) {
                if (e < off) sb[1024 + (slot << 6) + e] += sb[1024 + (slot << 6) + e + off];
                __syncthreads();
            }
            if (e == 0) {
                float dv = 0.5f * sb[1024 + (slot << 6)];
                if (!half) g_dx[row] = dv; else g_dy[row] = dv;
            }
        }
    }

    grid_bar();

    // ---- phase 3: C build. 128x128 tiles ----------------------------------
    for (int tt = 0; tt < 8; tt++) {
        int tile = b + (tt << 7);
        int n  = tile >> 8;
        int rem = tile & 255;
        int i0 = (rem >> 4) << 7;
        int j0 = (rem & 15) << 7;
        float acc[16];
        #pragma unroll
        for (int q = 0; q < 16; q++) acc[q] = 0.0f;

        #pragma unroll
        for (int ks = 0; ks < 64; ks += 32) {
            __syncthreads();
            {
                int i = t >> 3, kq = t & 7;
                float4 xa = *(const float4*)(g_XS + (size_t)(n * PP + i0 + i) * DD + ks + (kq << 2));
                float4 yb = *(const float4*)(y    + (size_t)(n * PP + j0 + i) * DD + ks + (kq << 2));
                int k0 = kq << 2;
                sa[(k0+0)*132 + i] = xa.x;  sa[(k0+1)*132 + i] = xa.y;
                sa[(k0+2)*132 + i] = xa.z;  sa[(k0+3)*132 + i] = xa.w;
                sb[(k0+0)*132 + i] = yb.x;  sb[(k0+1)*132 + i] = yb.y;
                sb[(k0+2)*132 + i] = yb.z;  sb[(k0+3)*132 + i] = yb.w;
            }
            __syncthreads();
            int cx = t & 31, cy = t >> 5;
            #pragma unroll
            for (int k = 0; k < 32; k++) {
                float4 a4 = *(const float4*)&sa[k*132 + (cy << 2)];
                float4 b4 = *(const float4*)&sb[k*132 + (cx << 2)];
                acc[ 0] = fmaf(a4.x, b4.x, acc[ 0]);
                acc[ 1] = fmaf(a4.x, b4.y, acc[ 1]);
                acc[ 2] = fmaf(a4.x, b4.z, acc[ 2]);
                acc[ 3] = fmaf(a4.x, b4.w, acc[ 3]);
                acc[ 4] = fmaf(a4.y, b4.x, acc[ 4]);
                acc[ 5] = fmaf(a4.y, b4.y, acc[ 5]);
                acc[ 6] = fmaf(a4.y, b4.z, acc[ 6]);
                acc[ 7] = fmaf(a4.y, b4.w, acc[ 7]);
                acc[ 8] = fmaf(a4.z, b4.x, acc[ 8]);
                acc[ 9] = fmaf(a4.z, b4.y, acc[ 9]);
                acc[10] = fmaf(a4.z, b4.z, acc[10]);
                acc[11] = fmaf(a4.z, b4.w, acc[11]);
                acc[12] = fmaf(a4.w, b4.x, acc[12]);
                acc[13] = fmaf(a4.w, b4.y, acc[13]);
                acc[14] = fmaf(a4.w, b4.z, acc[14]);
                acc[15] = fmaf(a4.w, b4.w, acc[15]);
            }
        }
        int cx = t & 31, cy = t >> 5;
        float dxr[4], dyr[4];
        #pragma unroll
        for (int q = 0; q < 4; q++) {
            dxr[q] = g_dx[n * PP + i0 + (cy << 2) + q];
            dyr[q] = g_dy[n * PP + j0 + (cx << 2) + q];
        }
        #pragma unroll
        for (int a = 0; a < 4; a++) {
            float4 o;
            o.x = dxr[a] + dyr[0] - acc[(a << 2) + 0];
            o.y = dxr[a] + dyr[1] - acc[(a << 2) + 1];
            o.z = dxr[a] + dyr[2] - acc[(a << 2) + 2];
            o.w = dxr[a] + dyr[3] - acc[(a << 2) + 3];
            *(float4*)(C + (size_t)(n * PP + i0 + (cy << 2) + a) * PP + j0 + (cx << 2)) = o;
        }
    }

    grid_bar();

    // ---- phase 4: Sinkhorn iterations, fused single-C-read ----------------
    const int n_pass = b >> 5;
    const int sub    = b & 31;
    const float* Cn  = C + ((size_t)n_pass << 22);
    bool active = true;

    for (int it = 0; it < MAXIT; it++) {
        // stage scaled v
        sv[t]        = g_v[(n_pass << 11) + t] * SCL;
        sv[t + 1024] = g_v[(n_pass << 11) + 1024 + t] * SCL;
        __syncthreads();

        const float4* vs4 = (const float4*)sv;
        float cm0 = MNEG, cs0 = 0.0f;    // column accumulators: cols 2t, 2t+1
        float cm1 = MNEG, cs1 = 0.0f;

        #pragma unroll 1
        for (int band = 0; band < 4; band++) {
            int r0 = (sub << 6) + (band << 4);
            // ===== row phase: 16 rows x 64 threads, stream C from L2 ======
            {
                int rr  = t >> 6;         // row within band (0..15)
                int cth = t & 63;         // thread within row
                const float4* Cr = (const float4*)Cn + (size_t)(r0 + rr) * 512;
                float m = MNEG, s = 0.0f;
                float4 ca = Cr[cth];
                float4 cb = Cr[cth + 64];
                #pragma unroll
                for (int k = 0; k < 4; k++) {
                    float4 na, nb;
                    if (k < 3) {
                        na = Cr[cth + (k << 7) + 128];
                        nb = Cr[cth + (k << 7) + 192];
                    }
                    float4 va = vs4[cth + (k << 7)];
                    float4 vb = vs4[cth + (k << 7) + 64];
                    float z0 = fmaf(ca.x, -SCL, va.x);
                    float z1 = fmaf(ca.y, -SCL, va.y);
                    float z2 = fmaf(ca.z, -SCL, va.z);
                    float z3 = fmaf(ca.w, -SCL, va.w);
                    float z4 = fmaf(cb.x, -SCL, vb.x);
                    float z5 = fmaf(cb.y, -SCL, vb.y);
                    float z6 = fmaf(cb.z, -SCL, vb.z);
                    float z7 = fmaf(cb.w, -SCL, vb.w);
                    float mc = fmaxf(fmaxf(fmaxf(z0, z1), fmaxf(z2, z3)),
                                     fmaxf(fmaxf(z4, z5), fmaxf(z6, z7)));
                    float sc = ex2f(z0 - mc) + ex2f(z1 - mc)
                             + ex2f(z2 - mc) + ex2f(z3 - mc)
                             + ex2f(z4 - mc) + ex2f(z5 - mc)
                             + ex2f(z6 - mc) + ex2f(z7 - mc);
                    lse_merge2(m, s, mc, sc);
                    ca = na; cb = nb;
                }
                #pragma unroll
                for (int off = 16; off > 0; off >>= 1) {
                    float mo = __shfl_xor_sync(0xffffffffu, m, off);
                    float so = __shfl_xor_sync(0xffffffffu, s, off);
                    lse_merge2(m, s, mo, so);
                }
                if (lane == 0) { pm2m[w] = m; pm2s[w] = s; }
            }
            __syncthreads();
            if (t < 16) {
                float M = pm2m[t << 1],       S = pm2s[t << 1];
                lse_merge2(M, S, pm2m[(t << 1) + 1], pm2s[(t << 1) + 1]);
                float unew = UC0 - ELN2 * (M + log2f(S));
                int gr = (n_pass << 11) + r0 + t;
                g_duabs[gr] = fabsf(unew - g_u[gr]);
                g_u[gr] = unew;
                su[t] = unew * SCL;
            }
            __syncthreads();
            // ===== column phase: re-read band from L1, cols (2t, 2t+1) ====
            {
                const float2* Cc2 = (const float2*)(Cn + (size_t)r0 * PP);
                #pragma unroll
                for (int half = 0; half < 2; half++) {
                    int rb = half << 3;
                    float z[8], zz[8];
                    #pragma unroll
                    for (int q = 0; q < 8; q++) {
                        float uq = su[rb + q];
                        float2 c2 = Cc2[(size_t)(rb + q) * 1024 + t];
                        z[q]  = fmaf(c2.x, -SCL, uq);
                        zz[q] = fmaf(c2.y, -SCL, uq);
                    }
                    float mc = fmaxf(fmaxf(fmaxf(z[0], z[1]), fmaxf(z[2], z[3])),
                                     fmaxf(fmaxf(z[4], z[5]), fmaxf(z[6], z[7])));
                    float sc = ex2f(z[0]-mc) + ex2f(z[1]-mc) + ex2f(z[2]-mc) + ex2f(z[3]-mc)
                             + ex2f(z[4]-mc) + ex2f(z[5]-mc) + ex2f(z[6]-mc) + ex2f(z[7]-mc);
                    lse_merge2(cm0, cs0, mc, sc);
                    float mc2 = fmaxf(fmaxf(fmaxf(zz[0], zz[1]), fmaxf(zz[2], zz[3])),
                                      fmaxf(fmaxf(zz[4], zz[5]), fmaxf(zz[6], zz[7])));
                    float sc2 = ex2f(zz[0]-mc2) + ex2f(zz[1]-mc2) + ex2f(zz[2]-mc2) + ex2f(zz[3]-mc2)
                              + ex2f(zz[4]-mc2) + ex2f(zz[5]-mc2) + ex2f(zz[6]-mc2) + ex2f(zz[7]-mc2);
                    lse_merge2(cm1, cs1, mc2, sc2);
                }
            }
        }
        // write column partials (coalesced float2)
        {
            float2 pmv; pmv.x = cm0; pmv.y = cm1;
            float2 psv; psv.x = cs0; psv.y = cs1;
            ((float2*)(g_pm + (size_t)b * PP))[t] = pmv;
            ((float2*)(g_ps + (size_t)b * PP))[t] = psv;
        }
        grid_bar();

        // ===== merge: warp w merges cols j0+w and j0+w+32 over 32 blocks ===
        {
            int j0 = sub << 6;
            #pragma unroll
            for (int rep = 0; rep < 2; rep++) {
                int col = j0 + w + (rep << 5);
                size_t pidx = (size_t)(((n_pass << 5) + lane) << 11) + col;
                float mm = g_pm[pidx];
                float ss = g_ps[pidx];
                #pragma unroll
                for (int off = 16; off > 0; off >>= 1) {
                    float mo = __shfl_xor_sync(0xffffffffu, mm, off);
                    float so = __shfl_xor_sync(0xffffffffu, ss, off);
                    lse_merge2(mm, ss, mo, so);
                }
                if (lane == 0)
                    g_v[(n_pass << 11) + col] = UC0 - ELN2 * (mm + log2f(ss));
            }
        }

        // ===== convergence: shuffle-based replicated reduction =============
        {
            float ea = 0.0f;
            #pragma unroll
            for (int q = 0; q < 8; q++) ea += g_duabs[t + (q << 10)];
            #pragma unroll
            for (int off = 16; off > 0; off >>= 1)
                ea += __shfl_xor_sync(0xffffffffu, ea, off);
            if (lane == 0) pm2m[w] = ea;
            __syncthreads();
            if (w == 0) {
                float v2 = pm2m[lane];
                #pragma unroll
                for (int off = 16; off > 0; off >>= 1)
                    v2 += __shfl_xor_sync(0xffffffffu, v2, off);
                if (lane == 0) s_err[0] = v2;
            }
            __syncthreads();
            active = (s_err[0] * 0.25f >= THRESHV);
        }
        grid_bar();
        if (!active) break;
    }

    // ---- phase 5: pi = exp2(u2+v2-C*SCL), cost partials --------------------
    {
        const float4* C4n = (const float4*)Cn;
        sv[t]        = g_v[(n_pass << 11) + t] * SCL;
        sv[t + 1024] = g_v[(n_pass << 11) + 1024 + t] * SCL;
        if (t < 64) sa[t] = g_u[(n_pass << 11) + (sub << 6) + t] * SCL;
        __syncthreads();
        const float4* vs4 = (const float4*)sv;
        const float4* Cb4 = C4n + (size_t)(sub << 6) * 512;
        float4* pi4 = (float4*)pi + (size_t)(n_pass * PP + (sub << 6)) * 512;
        float accc = 0.0f;
        #pragma unroll 4
        for (int k2 = 0; k2 < 32; k2++) {
            int idx = t + (k2 << 10);
            int row = idx >> 9;
            int c4  = idx & 511;
            float4 cc = Cb4[(size_t)row * 512 + c4];
            float  uu = sa[row];
            float4 vv = vs4[c4];
            float p0 = ex2f(fmaf(cc.x, -SCL, uu + vv.x));
            float p1 = ex2f(fmaf(cc.y, -SCL, uu + vv.y));
            float p2 = ex2f(fmaf(cc.z, -SCL, uu + vv.z));
            float p3 = ex2f(fmaf(cc.w, -SCL, uu + vv.w));
            float4 po; po.x = p0; po.y = p1; po.z = p2; po.w = p3;
            pi4[(size_t)row * 512 + c4] = po;
            accc = fmaf(p0, cc.x, accc);
            accc = fmaf(p1, cc.y, accc);
            accc = fmaf(p2, cc.z, accc);
            accc = fmaf(p3, cc.w, accc);
        }
        __syncthreads();
        sb[t] = accc;
        __syncthreads();
        for (int off = 512; off > 0; off >>= 1) {
            if (t < off) sb[t] += sb[t + off];
            __syncthreads();
        }
        if (t == 0) g_cpart[b] = sb[0];
    }
    grid_bar();
    if (b == 0 && t == 0) {
        #pragma unroll
        for (int n = 0; n < NB; n++) {
            float c = 0.0f;
            for (int q = 0; q < 32; q++) c += g_cpart[(n << 5) + q];
            cost[n] = c;
        }
    }
}

// ---------------- launch ---------------------------------------------------
extern "C" void kernel_launch(void* const* d_in, const int* in_sizes, int n_in,
                              void* d_out, int out_size) {
    const float* x = (const float*)d_in[0];   // [N,P1,D]
    const float* y = (const float*)d_in[1];   // [N,P2,D]
    const float* M = (const float*)d_in[2];   // [D,D]
    float* out  = (float*)d_out;              // cost[4] | pi | C
    float* cost = out;
    float* pi   = out + 4;
    float* C    = out + 4 + (size_t)NPITEMS;

    sinkhorn_all<<<NBLK, NT>>>(x, y, M, cost, pi, C);
}